// round 8
// baseline (speedup 1.0000x reference)
#include <cuda_runtime.h>
#include <cstdint>

#define NN 50000
#define NE 600000

// ---------------- scratch (device globals; no allocation allowed) ------------
__device__ float w_deg [NN];
__device__ float w_dinv[NN];
__device__ __align__(16) float w_X [(size_t)NN * 128];
__device__ __align__(16) float w_H [(size_t)NN * 128];
__device__ __align__(16) float w_A [(size_t)NN * 128];
__device__ int   w_src[NE];
__device__ int   w_dst[NE];
__device__ int   w_is64;

// ---------------- edge index dtype normalization ------------------------------
__global__ void eg_detect(const int* __restrict__ raw) {
    __shared__ int nz;
    if (threadIdx.x == 0) nz = 0;
    __syncthreads();
    if (raw[2 * threadIdx.x + 1] != 0) atomicExch(&nz, 1);
    __syncthreads();
    if (threadIdx.x == 0) w_is64 = (nz == 0) ? 1 : 0;
}

__global__ void eg_convert(const void* __restrict__ ei) {
    int e = blockIdx.x * blockDim.x + threadIdx.x;
    if (e >= 2 * NE) return;
    long long v;
    if (w_is64) v = ((const long long*)ei)[e];
    else        v = (long long)((const int*)ei)[e];
    int vi = (int)v;
    if (vi < 0) vi = 0;
    if (vi >= NN) vi = NN - 1;
    if (e < NE) w_src[e] = vi;
    else        w_dst[e - NE] = vi;
}

// ---------------- degree / norm -----------------------------------------------
__global__ void eg_deg_init() {
    int i = blockIdx.x * blockDim.x + threadIdx.x;
    if (i < NN) w_deg[i] = 1.0f;
}
__global__ void eg_deg_count() {
    int e = blockIdx.x * blockDim.x + threadIdx.x;
    if (e < NE) atomicAdd(&w_deg[w_dst[e]], 1.0f);
}
__global__ void eg_dinv() {
    int i = blockIdx.x * blockDim.x + threadIdx.x;
    if (i < NN) w_dinv[i] = rsqrtf(w_deg[i]);
}

// ---------------- tiled GEMM: H[n, DOUT] = X[n, DIN] @ W[DIN, DOUT] ------------
// blockDim = 128. Each block computes NPB=16 nodes. CPT = 128/DOUT node-slices
// run in parallel; each thread owns column (tid % DOUT) for NR = NPB/CPT nodes.
template<int DIN, int DOUT>
__global__ void eg_gemm2(const float* __restrict__ X,
                         const float* __restrict__ W,
                         float* __restrict__ H) {
    constexpr int NPB = 16;
    constexpr int CPT = 128 / DOUT;
    constexpr int NR  = NPB / CPT;

    __shared__ float sW[DIN * DOUT];
    __shared__ float sx[NPB * DIN];

    const int tid = threadIdx.x;
    const int col = tid % DOUT;
    const int sub = tid / DOUT;
    const int node0 = blockIdx.x * NPB;

    for (int i = tid; i < DIN * DOUT; i += 128) sW[i] = W[i];
    for (int i = tid; i < NPB * DIN; i += 128) {
        int r = i / DIN, c = i % DIN;
        int node = node0 + r;
        sx[i] = (node < NN) ? X[(size_t)node * DIN + c] : 0.0f;
    }
    __syncthreads();

    float acc[NR];
    #pragma unroll
    for (int j = 0; j < NR; j++) acc[j] = 0.0f;

    for (int k = 0; k < DIN; k++) {
        float wk = sW[k * DOUT + col];
        #pragma unroll
        for (int j = 0; j < NR; j++)
            acc[j] = fmaf(sx[(sub + j * CPT) * DIN + k], wk, acc[j]);
    }

    #pragma unroll
    for (int j = 0; j < NR; j++) {
        int node = node0 + sub + j * CPT;
        if (node < NN) H[(size_t)node * DOUT + col] = acc[j];
    }
}

// ---------------- self-loop term: A = dinv^2 * H (float4) -----------------------
template<int DOUT>
__global__ void eg_self4(const float* __restrict__ H,
                         float* __restrict__ A) {
    constexpr int VPR = DOUT / 4;
    long long i4 = (long long)blockIdx.x * blockDim.x + threadIdx.x;
    if (i4 >= (long long)NN * VPR) return;
    int node = (int)(i4 / VPR);
    float di = w_dinv[node];
    float s  = di * di;
    float4 v = reinterpret_cast<const float4*>(H)[i4];
    v.x *= s; v.y *= s; v.z *= s; v.w *= s;
    reinterpret_cast<float4*>(A)[i4] = v;
}

// ---------------- edge scatter: A[dst] += dinv[s]dinv[d] * H[src] (float4) ------
template<int DOUT>
__global__ void eg_scatter4(const float* __restrict__ H,
                            float* __restrict__ A) {
    constexpr int TPE = DOUT / 4;
    long long gid = (long long)blockIdx.x * blockDim.x + threadIdx.x;
    if (gid >= (long long)NE * TPE) return;
    int e    = (int)(gid / TPE);
    int lane = (int)(gid % TPE);

    int s = __ldg(&w_src[e]);
    int d = __ldg(&w_dst[e]);
    float wgt = __ldg(&w_dinv[s]) * __ldg(&w_dinv[d]);

    float4 v = reinterpret_cast<const float4*>(H + (size_t)s * DOUT)[lane];
    float* a = A + (size_t)d * DOUT + (size_t)lane * 4;
    atomicAdd(a + 0, wgt * v.x);
    atomicAdd(a + 1, wgt * v.y);
    atomicAdd(a + 2, wgt * v.z);
    atomicAdd(a + 3, wgt * v.w);
}

// ---------------- activation: X = relu(A + b) -----------------------------------
__global__ void eg_act(const float* __restrict__ A,
                       const float* __restrict__ b,
                       float* __restrict__ X, int dout) {
    long long idx = (long long)blockIdx.x * blockDim.x + threadIdx.x;
    if (idx >= (long long)NN * dout) return;
    int c = (int)(idx % dout);
    float v = A[idx] + b[c];
    X[idx] = v > 0.0f ? v : 0.0f;
}

// ---------------- MLP head: X3(32) -> 16 relu -> 1 -> sigmoid -------------------
__global__ void eg_head(const float* __restrict__ X3,
                        const float* __restrict__ Wf1, const float* __restrict__ bf1,
                        const float* __restrict__ Wf2, const float* __restrict__ bf2,
                        float* __restrict__ out) {
    int node = blockIdx.x * blockDim.x + threadIdx.x;
    if (node >= NN) return;
    const float* xr = X3 + (size_t)node * 32;

    float z = bf2[0];
    for (int j = 0; j < 16; j++) {
        float a = bf1[j];
        for (int k = 0; k < 32; k++)
            a += xr[k] * Wf1[k * 16 + j];
        if (a < 0.0f) a = 0.0f;
        z += a * Wf2[j];
    }
    out[node] = 1.0f / (1.0f + expf(-z));
}

// ---------------- launch ---------------------------------------------------------
static inline unsigned gsz(long long n, int t) { return (unsigned)((n + t - 1) / t); }

extern "C" void kernel_launch(void* const* d_in, const int* in_sizes, int n_in,
                              void* d_out, int out_size) {
    const float* x   = (const float*)d_in[0];
    const void*  ei  = d_in[1];
    const float* W1  = (const float*)d_in[2];
    const float* b1  = (const float*)d_in[3];
    const float* W2  = (const float*)d_in[4];
    const float* b2  = (const float*)d_in[5];
    const float* W3  = (const float*)d_in[6];
    const float* b3  = (const float*)d_in[7];
    const float* Wf1 = (const float*)d_in[8];
    const float* bf1 = (const float*)d_in[9];
    const float* Wf2 = (const float*)d_in[10];
    const float* bf2 = (const float*)d_in[11];
    float* out = (float*)d_out;

    const int T = 256;
    const unsigned GB = gsz(NN, 16);     // gemm blocks (16 nodes per block)

    eg_detect <<<1, 256>>>((const int*)ei);
    eg_convert<<<gsz(2LL * NE, T), T>>>(ei);

    eg_deg_init <<<gsz(NN, T), T>>>();
    eg_deg_count<<<gsz(NE, T), T>>>();
    eg_dinv     <<<gsz(NN, T), T>>>();

    // ---- layer 1: x(44) -> 128 ----
    eg_gemm2<44, 128><<<GB, 128>>>(x, W1, w_H);
    eg_self4<128>   <<<gsz((long long)NN * 32, T), T>>>(w_H, w_A);
    eg_scatter4<128><<<gsz((long long)NE * 32, T), T>>>(w_H, w_A);
    eg_act          <<<gsz((long long)NN * 128, T), T>>>(w_A, b1, w_X, 128);

    // ---- layer 2: 128 -> 64 ----
    eg_gemm2<128, 64><<<GB, 128>>>(w_X, W2, w_H);
    eg_self4<64>    <<<gsz((long long)NN * 16, T), T>>>(w_H, w_A);
    eg_scatter4<64> <<<gsz((long long)NE * 16, T), T>>>(w_H, w_A);
    eg_act          <<<gsz((long long)NN * 64, T), T>>>(w_A, b2, w_X, 64);

    // ---- layer 3: 64 -> 32 ----
    eg_gemm2<64, 32><<<GB, 128>>>(w_X, W3, w_H);
    eg_self4<32>    <<<gsz((long long)NN * 8, T), T>>>(w_H, w_A);
    eg_scatter4<32> <<<gsz((long long)NE * 8, T), T>>>(w_H, w_A);
    eg_act          <<<gsz((long long)NN * 32, T), T>>>(w_A, b3, w_X, 32);

    // ---- MLP head ----
    eg_head<<<gsz(NN, T), T>>>(w_X, Wf1, bf1, Wf2, bf2, out);
}

// round 9
// speedup vs baseline: 4.4060x; 4.4060x over previous
#include <cuda_runtime.h>
#include <cstdint>

#define NN 50000
#define NE 600000
#define SCAN_T 1024
#define CHUNK ((NN + SCAN_T - 1) / SCAN_T)

// ---------------- scratch (device globals; no allocation allowed) ------------
__device__ float w_deg [NN];
__device__ float w_dinv[NN];
__device__ __align__(16) float w_X [(size_t)NN * 128];   // layer input (post-act)
__device__ __align__(16) float w_H [(size_t)NN * 128];   // gemm output
__device__ int   w_src[NE];
__device__ int   w_dst[NE];
__device__ int   w_is64;
// CSR (by destination)
__device__ int   g_off [NN + 1];
__device__ int   g_cur [NN];
__device__ int   g_esrc[NE];
__device__ float g_ew  [NE];

// ---------------- edge index dtype normalization ------------------------------
__global__ void eg_detect(const int* __restrict__ raw) {
    __shared__ int nz;
    if (threadIdx.x == 0) nz = 0;
    __syncthreads();
    if (raw[2 * threadIdx.x + 1] != 0) atomicExch(&nz, 1);
    __syncthreads();
    if (threadIdx.x == 0) w_is64 = (nz == 0) ? 1 : 0;
}

__global__ void eg_convert(const void* __restrict__ ei) {
    int e = blockIdx.x * blockDim.x + threadIdx.x;
    if (e >= 2 * NE) return;
    long long v;
    if (w_is64) v = ((const long long*)ei)[e];
    else        v = (long long)((const int*)ei)[e];
    int vi = (int)v;
    if (vi < 0) vi = 0;
    if (vi >= NN) vi = NN - 1;
    if (e < NE) w_src[e] = vi;
    else        w_dst[e - NE] = vi;
}

// ---------------- degree / norm -----------------------------------------------
__global__ void eg_deg_init() {
    int i = blockIdx.x * blockDim.x + threadIdx.x;
    if (i < NN) w_deg[i] = 1.0f;              // self loop
}
__global__ void eg_deg_count() {
    int e = blockIdx.x * blockDim.x + threadIdx.x;
    if (e < NE) atomicAdd(&w_deg[w_dst[e]], 1.0f);
}
__global__ void eg_dinv() {
    int i = blockIdx.x * blockDim.x + threadIdx.x;
    if (i < NN) w_dinv[i] = rsqrtf(w_deg[i]);
}

// ---------------- CSR offsets: exclusive scan of in-degree (deg-1) -------------
__global__ void eg_scan() {
    __shared__ int ssum[SCAN_T];
    int t  = threadIdx.x;
    int lo = t * CHUNK;
    int hi = lo + CHUNK; if (hi > NN) hi = NN; if (lo > NN) lo = NN;

    int s = 0;
    for (int i = lo; i < hi; i++) s += (int)w_deg[i] - 1;
    ssum[t] = s;
    __syncthreads();
    for (int d = 1; d < SCAN_T; d <<= 1) {
        int v = (t >= d) ? ssum[t - d] : 0;
        __syncthreads();
        ssum[t] += v;
        __syncthreads();
    }
    int run = (t == 0) ? 0 : ssum[t - 1];
    for (int i = lo; i < hi; i++) {
        g_off[i] = run;
        g_cur[i] = run;
        run += (int)w_deg[i] - 1;
    }
    if (t == SCAN_T - 1) g_off[NN] = run;     // == NE
}

// ---------------- CSR fill: per-edge (src, dinv[s]*dinv[d]) --------------------
__global__ void eg_fill() {
    int e = blockIdx.x * blockDim.x + threadIdx.x;
    if (e >= NE) return;
    int s = w_src[e];
    int d = w_dst[e];
    int pos = atomicAdd(&g_cur[d], 1);
    g_esrc[pos] = s;
    g_ew[pos]   = w_dinv[s] * w_dinv[d];
}

// ---------------- plain GEMM (unchanged from passing baseline) -----------------
__global__ void eg_gemm(const float* __restrict__ X,
                        const float* __restrict__ W,
                        float* __restrict__ H,
                        int din, int dout) {
    long long idx = (long long)blockIdx.x * blockDim.x + threadIdx.x;
    if (idx >= (long long)NN * dout) return;
    int node = (int)(idx / dout);
    int col  = (int)(idx % dout);
    const float* xr = X + (size_t)node * din;
    float acc = 0.0f;
    for (int k = 0; k < din; k++)
        acc += xr[k] * W[(size_t)k * dout + col];
    H[idx] = acc;
}

// ---------------- gather aggregation + fused bias/ReLU -------------------------
// X[n] = relu( dinv[n]^2 * H[n] + sum_{e: dst=n} w_e * H[src_e] + b )
template<int DOUT>
__global__ void eg_agg(const float* __restrict__ H,
                       const float* __restrict__ b,
                       float* __restrict__ X) {
    constexpr int VPR = DOUT / 4;             // float4 lanes per node
    long long gt = (long long)blockIdx.x * blockDim.x + threadIdx.x;
    int node = (int)(gt / VPR);
    int lane = (int)(gt % VPR);
    if (node >= NN) return;

    const float4* H4 = reinterpret_cast<const float4*>(H);

    float di = w_dinv[node];
    float s2 = di * di;
    float4 acc = H4[(size_t)node * VPR + lane];
    acc.x *= s2; acc.y *= s2; acc.z *= s2; acc.w *= s2;

    int beg = g_off[node];
    int end = g_off[node + 1];
    for (int i = beg; i < end; i++) {
        int   s = __ldg(&g_esrc[i]);
        float w = __ldg(&g_ew[i]);
        float4 v = H4[(size_t)s * VPR + lane];
        acc.x = fmaf(w, v.x, acc.x);
        acc.y = fmaf(w, v.y, acc.y);
        acc.z = fmaf(w, v.z, acc.z);
        acc.w = fmaf(w, v.w, acc.w);
    }

    float4 bb = reinterpret_cast<const float4*>(b)[lane];
    acc.x = fmaxf(acc.x + bb.x, 0.0f);
    acc.y = fmaxf(acc.y + bb.y, 0.0f);
    acc.z = fmaxf(acc.z + bb.z, 0.0f);
    acc.w = fmaxf(acc.w + bb.w, 0.0f);
    reinterpret_cast<float4*>(X)[(size_t)node * VPR + lane] = acc;
}

// ---------------- MLP head: X3(32) -> 16 relu -> 1 -> sigmoid -------------------
__global__ void eg_head(const float* __restrict__ X3,
                        const float* __restrict__ Wf1, const float* __restrict__ bf1,
                        const float* __restrict__ Wf2, const float* __restrict__ bf2,
                        float* __restrict__ out) {
    int node = blockIdx.x * blockDim.x + threadIdx.x;
    if (node >= NN) return;
    const float* xr = X3 + (size_t)node * 32;

    float z = bf2[0];
    for (int j = 0; j < 16; j++) {
        float a = bf1[j];
        for (int k = 0; k < 32; k++)
            a += xr[k] * Wf1[k * 16 + j];
        if (a < 0.0f) a = 0.0f;
        z += a * Wf2[j];
    }
    out[node] = 1.0f / (1.0f + expf(-z));
}

// ---------------- launch ---------------------------------------------------------
static inline unsigned gsz(long long n, int t) { return (unsigned)((n + t - 1) / t); }

extern "C" void kernel_launch(void* const* d_in, const int* in_sizes, int n_in,
                              void* d_out, int out_size) {
    const float* x   = (const float*)d_in[0];
    const void*  ei  = d_in[1];
    const float* W1  = (const float*)d_in[2];
    const float* b1  = (const float*)d_in[3];
    const float* W2  = (const float*)d_in[4];
    const float* b2  = (const float*)d_in[5];
    const float* W3  = (const float*)d_in[6];
    const float* b3  = (const float*)d_in[7];
    const float* Wf1 = (const float*)d_in[8];
    const float* bf1 = (const float*)d_in[9];
    const float* Wf2 = (const float*)d_in[10];
    const float* bf2 = (const float*)d_in[11];
    float* out = (float*)d_out;

    const int T = 256;

    eg_detect <<<1, 256>>>((const int*)ei);
    eg_convert<<<gsz(2LL * NE, T), T>>>(ei);

    eg_deg_init <<<gsz(NN, T), T>>>();
    eg_deg_count<<<gsz(NE, T), T>>>();
    eg_dinv     <<<gsz(NN, T), T>>>();

    // CSR build
    eg_scan<<<1, SCAN_T>>>();
    eg_fill<<<gsz(NE, T), T>>>();

    // ---- layer 1: x(44) -> 128 ----
    eg_gemm    <<<gsz((long long)NN * 128, T), T>>>(x, W1, w_H, 44, 128);
    eg_agg<128><<<gsz((long long)NN * 32, T), T>>>(w_H, b1, w_X);

    // ---- layer 2: 128 -> 64 ----
    eg_gemm   <<<gsz((long long)NN * 64, T), T>>>(w_X, W2, w_H, 128, 64);
    eg_agg<64><<<gsz((long long)NN * 16, T), T>>>(w_H, b2, w_X);

    // ---- layer 3: 64 -> 32 ----
    eg_gemm   <<<gsz((long long)NN * 32, T), T>>>(w_X, W3, w_H, 64, 32);
    eg_agg<32><<<gsz((long long)NN * 8, T), T>>>(w_H, b3, w_X);

    // ---- MLP head ----
    eg_head<<<gsz(NN, T), T>>>(w_X, Wf1, bf1, Wf2, bf2, out);
}

// round 10
// speedup vs baseline: 4.5405x; 1.0305x over previous
#include <cuda_runtime.h>
#include <cstdint>

#define NN 50000
#define NE 600000
#define SCAN_T 1024
#define CHUNK ((NN + SCAN_T - 1) / SCAN_T)

// ---------------- scratch (device globals; no allocation allowed) ------------
__device__ float w_deg [NN];
__device__ float w_dinv[NN];
__device__ __align__(16) float w_X [(size_t)NN * 128];   // layer input (post-act)
__device__ __align__(16) float w_H [(size_t)NN * 128];   // gemm output
__device__ int   w_src[NE];
__device__ int   w_dst[NE];
__device__ int   w_is64;
// CSR (by destination)
__device__ int   g_off [NN + 1];
__device__ int   g_cur [NN];
__device__ int   g_esrc[NE];
__device__ float g_ew  [NE];

// ---------------- edge index dtype normalization ------------------------------
__global__ void eg_detect(const int* __restrict__ raw) {
    __shared__ int nz;
    if (threadIdx.x == 0) nz = 0;
    __syncthreads();
    if (raw[2 * threadIdx.x + 1] != 0) atomicExch(&nz, 1);
    __syncthreads();
    if (threadIdx.x == 0) w_is64 = (nz == 0) ? 1 : 0;
}

__global__ void eg_convert(const void* __restrict__ ei) {
    int e = blockIdx.x * blockDim.x + threadIdx.x;
    if (e >= 2 * NE) return;
    long long v;
    if (w_is64) v = ((const long long*)ei)[e];
    else        v = (long long)((const int*)ei)[e];
    int vi = (int)v;
    if (vi < 0) vi = 0;
    if (vi >= NN) vi = NN - 1;
    if (e < NE) w_src[e] = vi;
    else        w_dst[e - NE] = vi;
}

// ---------------- degree / norm -----------------------------------------------
__global__ void eg_deg_init() {
    int i = blockIdx.x * blockDim.x + threadIdx.x;
    if (i < NN) w_deg[i] = 1.0f;              // self loop
}
__global__ void eg_deg_count() {
    int e = blockIdx.x * blockDim.x + threadIdx.x;
    if (e < NE) atomicAdd(&w_deg[w_dst[e]], 1.0f);
}
__global__ void eg_dinv() {
    int i = blockIdx.x * blockDim.x + threadIdx.x;
    if (i < NN) w_dinv[i] = rsqrtf(w_deg[i]);
}

// ---------------- CSR offsets: exclusive scan of in-degree (deg-1) -------------
__global__ void eg_scan() {
    __shared__ int ssum[SCAN_T];
    int t  = threadIdx.x;
    int lo = t * CHUNK;
    int hi = lo + CHUNK; if (hi > NN) hi = NN; if (lo > NN) lo = NN;

    int s = 0;
    for (int i = lo; i < hi; i++) s += (int)w_deg[i] - 1;
    ssum[t] = s;
    __syncthreads();
    for (int d = 1; d < SCAN_T; d <<= 1) {
        int v = (t >= d) ? ssum[t - d] : 0;
        __syncthreads();
        ssum[t] += v;
        __syncthreads();
    }
    int run = (t == 0) ? 0 : ssum[t - 1];
    for (int i = lo; i < hi; i++) {
        g_off[i] = run;
        g_cur[i] = run;
        run += (int)w_deg[i] - 1;
    }
    if (t == SCAN_T - 1) g_off[NN] = run;     // == NE
}

// ---------------- CSR fill: per-edge (src, dinv[s]*dinv[d]) --------------------
__global__ void eg_fill() {
    int e = blockIdx.x * blockDim.x + threadIdx.x;
    if (e >= NE) return;
    int s = w_src[e];
    int d = w_dst[e];
    int pos = atomicAdd(&g_cur[d], 1);
    g_esrc[pos] = s;
    g_ew[pos]   = w_dinv[s] * w_dinv[d];
}

// ---------------- GEMM: H[n, DOUT] = X[n, DIN] @ W[DIN, DOUT] ------------------
// Compile-time dims, float4 row loads, 4 independent accumulator chains.
template<int DIN, int DOUT>
__global__ void eg_gemm3(const float* __restrict__ X,
                         const float* __restrict__ W,
                         float* __restrict__ H) {
    long long idx = (long long)blockIdx.x * blockDim.x + threadIdx.x;
    if (idx >= (long long)NN * DOUT) return;
    int node = (int)(idx / DOUT);
    int col  = (int)(idx % DOUT);
    const float4* x4 = reinterpret_cast<const float4*>(X + (size_t)node * DIN);

    float a0 = 0.0f, a1 = 0.0f, a2 = 0.0f, a3 = 0.0f;
    #pragma unroll
    for (int k4 = 0; k4 < DIN / 4; k4++) {
        float4 xv = x4[k4];
        a0 = fmaf(xv.x, W[(size_t)(4 * k4 + 0) * DOUT + col], a0);
        a1 = fmaf(xv.y, W[(size_t)(4 * k4 + 1) * DOUT + col], a1);
        a2 = fmaf(xv.z, W[(size_t)(4 * k4 + 2) * DOUT + col], a2);
        a3 = fmaf(xv.w, W[(size_t)(4 * k4 + 3) * DOUT + col], a3);
    }
    H[idx] = (a0 + a1) + (a2 + a3);
}

// ---------------- gather aggregation + fused bias/ReLU (block per node) --------
// X[n] = relu( dinv[n]^2 * H[n] + sum_{e: dst=n} w_e * H[src_e] + b )
// blockDim == DOUT; thread = channel. Edge (src, w) staged via shared memory.
template<int DOUT>
__global__ void eg_agg2(const float* __restrict__ H,
                        const float* __restrict__ b,
                        float* __restrict__ X) {
    __shared__ int   s_i[64];
    __shared__ float s_v[64];
    const int node = blockIdx.x;
    const int tid  = threadIdx.x;

    float di  = w_dinv[node];
    float acc = di * di * H[(size_t)node * DOUT + tid];

    const int beg = g_off[node];
    const int end = g_off[node + 1];
    for (int base = beg; base < end; base += 64) {
        int cnt = end - base; if (cnt > 64) cnt = 64;
        __syncthreads();
        for (int i = tid; i < cnt; i += DOUT) {
            s_i[i] = g_esrc[base + i];
            s_v[i] = g_ew  [base + i];
        }
        __syncthreads();
        for (int i = 0; i < cnt; i++)
            acc = fmaf(s_v[i], H[(size_t)s_i[i] * DOUT + tid], acc);
    }
    X[(size_t)node * DOUT + tid] = fmaxf(acc + b[tid], 0.0f);
}

// ---------------- MLP head: X3(32) -> 16 relu -> 1 -> sigmoid -------------------
__global__ void eg_head(const float* __restrict__ X3,
                        const float* __restrict__ Wf1, const float* __restrict__ bf1,
                        const float* __restrict__ Wf2, const float* __restrict__ bf2,
                        float* __restrict__ out) {
    int node = blockIdx.x * blockDim.x + threadIdx.x;
    if (node >= NN) return;
    const float* xr = X3 + (size_t)node * 32;

    float z = bf2[0];
    for (int j = 0; j < 16; j++) {
        float a = bf1[j];
        for (int k = 0; k < 32; k++)
            a += xr[k] * Wf1[k * 16 + j];
        if (a < 0.0f) a = 0.0f;
        z += a * Wf2[j];
    }
    out[node] = 1.0f / (1.0f + expf(-z));
}

// ---------------- launch ---------------------------------------------------------
static inline unsigned gsz(long long n, int t) { return (unsigned)((n + t - 1) / t); }

extern "C" void kernel_launch(void* const* d_in, const int* in_sizes, int n_in,
                              void* d_out, int out_size) {
    const float* x   = (const float*)d_in[0];
    const void*  ei  = d_in[1];
    const float* W1  = (const float*)d_in[2];
    const float* b1  = (const float*)d_in[3];
    const float* W2  = (const float*)d_in[4];
    const float* b2  = (const float*)d_in[5];
    const float* W3  = (const float*)d_in[6];
    const float* b3  = (const float*)d_in[7];
    const float* Wf1 = (const float*)d_in[8];
    const float* bf1 = (const float*)d_in[9];
    const float* Wf2 = (const float*)d_in[10];
    const float* bf2 = (const float*)d_in[11];
    float* out = (float*)d_out;

    const int T = 256;

    eg_detect <<<1, 256>>>((const int*)ei);
    eg_convert<<<gsz(2LL * NE, T), T>>>(ei);

    eg_deg_init <<<gsz(NN, T), T>>>();
    eg_deg_count<<<gsz(NE, T), T>>>();
    eg_dinv     <<<gsz(NN, T), T>>>();

    // CSR build
    eg_scan<<<1, SCAN_T>>>();
    eg_fill<<<gsz(NE, T), T>>>();

    // ---- layer 1: x(44) -> 128 ----
    eg_gemm3<44, 128><<<gsz((long long)NN * 128, T), T>>>(x, W1, w_H);
    eg_agg2<128>     <<<NN, 128>>>(w_H, b1, w_X);

    // ---- layer 2: 128 -> 64 ----
    eg_gemm3<128, 64><<<gsz((long long)NN * 64, T), T>>>(w_X, W2, w_H);
    eg_agg2<64>      <<<NN, 64>>>(w_H, b2, w_X);

    // ---- layer 3: 64 -> 32 ----
    eg_gemm3<64, 32><<<gsz((long long)NN * 32, T), T>>>(w_X, W3, w_H);
    eg_agg2<32>     <<<NN, 32>>>(w_H, b3, w_X);

    // ---- MLP head ----
    eg_head<<<gsz(NN, T), T>>>(w_X, Wf1, bf1, Wf2, bf2, out);
}